// round 1
// baseline (speedup 1.0000x reference)
#include <cuda_runtime.h>
#include <math.h>

// ---------------- problem constants ----------------
#define FQ     2049          // freq bins
#define NT     1500          // frames
#define TLEN   1535976       // audio samples
#define NFFT   4096
#define HOP    1024
#define NSRC   4
#define NCHUNK 5
#define WINLEN 300
#define EPSV   1e-10f
#define SQEPS  1e-5f

// ---------------- device scratch (static, no allocation) ----------------
__device__ float2 g_mix[2 * FQ * NT];          // STFT of mixture  [c][f][t]
__device__ float  g_mag[2 * FQ * NT];          // |mix|            [c][f][t]
__device__ float  g_V[8 * FQ * NT];            // targets          [s*2+c][f][t]
__device__ float2 g_Y[8 * FQ * NT];            // wiener output    [s*2+c][f][t]
__device__ float  g_frames[8 * NT * NFFT];     // windowed irfft frames
__device__ float2 g_tw[NFFT / 2];              // e^{-2pi i j/4096}
__device__ float  g_win[NFFT];                 // periodic hann
__device__ int    g_cmax[NCHUNK];              // per-chunk max|x| (float bits)

// ---------------- helpers ----------------
__device__ __forceinline__ float2 cmul(float2 a, float2 b) {
    return make_float2(a.x * b.x - a.y * b.y, a.x * b.y + a.y * b.x);
}
__device__ __forceinline__ float2 cadd(float2 a, float2 b) {
    return make_float2(a.x + b.x, a.y + b.y);
}
__device__ __forceinline__ int rev12(int n) { return (int)(__brev((unsigned)n) >> 20); }

// in-place radix-2 DIT FFT, data pre-loaded bit-reversed in shared. sign=-1 fwd, +1 inv (unscaled)
__device__ void fft4096(float2* sh, int sign) {
    for (int half = 1; half <= 2048; half <<= 1) {
        int step = 2048 / half;
        for (int j = threadIdx.x; j < 2048; j += blockDim.x) {
            int k = j & (half - 1);
            int i0 = 2 * j - k;
            int i1 = i0 + half;
            float2 w = g_tw[k * step];
            if (sign > 0) w.y = -w.y;
            float2 u = sh[i0];
            float2 v = cmul(sh[i1], w);
            sh[i0] = make_float2(u.x + v.x, u.y + v.y);
            sh[i1] = make_float2(u.x - v.x, u.y - v.y);
        }
        __syncthreads();
    }
}

// ---------------- init: tables + chunk-max reset ----------------
__global__ void init_kernel() {
    int i = blockIdx.x * blockDim.x + threadIdx.x;
    if (i < NFFT / 2) {
        float s, c;
        sincospif(i * (1.0f / 2048.0f), &s, &c);
        g_tw[i] = make_float2(c, -s);
    }
    if (i < NFFT) {
        g_win[i] = 0.5f * (1.0f - cospif(i * (1.0f / 2048.0f)));
    }
    if (i < NCHUNK) g_cmax[i] = 0;
}

// ---------------- STFT (+ mag, + per-chunk max reduction) ----------------
__global__ __launch_bounds__(256) void stft_kernel(const float* __restrict__ audio) {
    __shared__ float2 sh[NFFT];
    __shared__ float smax[256];
    int t = blockIdx.x, c = blockIdx.y;
    for (int n = threadIdx.x; n < NFFT; n += 256) {
        int j = t * HOP + n - (NFFT / 2);
        if (j < 0) j = -j;
        if (j >= TLEN) j = 2 * (TLEN - 1) - j;
        float val = audio[c * TLEN + j] * g_win[n];
        sh[rev12(n)] = make_float2(val, 0.f);
    }
    __syncthreads();
    fft4096(sh, -1);
    float lmax = 0.f;
    for (int f = threadIdx.x; f <= NFFT / 2; f += 256) {
        float2 v = sh[f];
        int idx = (c * FQ + f) * NT + t;
        g_mix[idx] = v;
        float m = sqrtf(v.x * v.x + v.y * v.y);
        g_mag[idx] = m;
        lmax = fmaxf(lmax, m);
    }
    smax[threadIdx.x] = lmax;
    __syncthreads();
    for (int off = 128; off; off >>= 1) {
        if (threadIdx.x < off) smax[threadIdx.x] = fmaxf(smax[threadIdx.x], smax[threadIdx.x + off]);
        __syncthreads();
    }
    if (threadIdx.x == 0) atomicMax(&g_cmax[t / WINLEN], __float_as_int(smax[0]));
}

// ---------------- V = relu(W[s] @ mag[c])  (8 GEMMs 2049x1500x2049) ----------------
__global__ __launch_bounds__(256) void gemm_kernel(const float* __restrict__ Wmat) {
    const int sc = blockIdx.z;
    const int s = sc >> 1, c = sc & 1;
    const float* A = Wmat + s * FQ * FQ;    // [g][f]
    const float* B = g_mag + c * FQ * NT;   // [f][t]
    float* C = g_V + sc * FQ * NT;          // [g][t]

    __shared__ float As[16][64];
    __shared__ float Bs[16][64];

    int tid = threadIdx.x;
    int tx = tid & 15, ty = tid >> 4;
    int row0 = blockIdx.y * 64, col0 = blockIdx.x * 64;
    float acc[4][4];
#pragma unroll
    for (int i = 0; i < 4; i++)
#pragma unroll
        for (int j = 0; j < 4; j++) acc[i][j] = 0.f;

    for (int k0 = 0; k0 < FQ; k0 += 16) {
#pragma unroll
        for (int i = 0; i < 4; i++) {
            int lin = tid + i * 256;
            int m = lin >> 4, kk = lin & 15;
            int g = row0 + m, k = k0 + kk;
            As[kk][m] = (g < FQ && k < FQ) ? A[g * FQ + k] : 0.f;
        }
#pragma unroll
        for (int i = 0; i < 4; i++) {
            int lin = tid + i * 256;
            int kk = lin >> 6, n = lin & 63;
            int k = k0 + kk, tcol = col0 + n;
            Bs[kk][n] = (k < FQ && tcol < NT) ? B[k * NT + tcol] : 0.f;
        }
        __syncthreads();
#pragma unroll
        for (int kk = 0; kk < 16; kk++) {
            float a[4], b[4];
#pragma unroll
            for (int i = 0; i < 4; i++) a[i] = As[kk][ty * 4 + i];
#pragma unroll
            for (int j = 0; j < 4; j++) b[j] = Bs[kk][tx * 4 + j];
#pragma unroll
            for (int i = 0; i < 4; i++)
#pragma unroll
                for (int j = 0; j < 4; j++) acc[i][j] += a[i] * b[j];
        }
        __syncthreads();
    }
#pragma unroll
    for (int i = 0; i < 4; i++) {
        int g = row0 + ty * 4 + i;
        if (g >= FQ) continue;
#pragma unroll
        for (int j = 0; j < 4; j++) {
            int tcol = col0 + tx * 4 + j;
            if (tcol < NT) C[g * NT + tcol] = fmaxf(acc[i][j], 0.f);
        }
    }
}

// ---------------- Wiener EM, 1 iteration, per (freq, chunk) ----------------
__global__ __launch_bounds__(128) void wiener_kernel() {
    const int f = blockIdx.x, ck = blockIdx.y;
    const int tid = threadIdx.x;
    const float ma = fmaxf(1.0f, __int_as_float(g_cmax[ck]) * 0.1f);
    const float ima = 1.0f / ma;

    // pass A: accumulate R (hermitian 2x2 per source) and sum_t v
    float r00[NSRC], r11[NSRC], r01r[NSRC], r01i[NSRC], vs[NSRC];
#pragma unroll
    for (int s = 0; s < NSRC; s++) { r00[s] = r11[s] = r01r[s] = r01i[s] = vs[s] = 0.f; }

    for (int t = tid; t < WINLEN; t += 128) {
        int tg = ck * WINLEN + t;
        float2 x0 = g_mix[(0 * FQ + f) * NT + tg];
        float2 x1 = g_mix[(1 * FQ + f) * NT + tg];
        float a0 = sqrtf(x0.x * x0.x + x0.y * x0.y);
        float a1 = sqrtf(x1.x * x1.x + x1.y * x1.y);
        float2 p0 = (a0 > 0.f) ? make_float2(x0.x / a0, x0.y / a0) : make_float2(1.f, 0.f);
        float2 p1 = (a1 > 0.f) ? make_float2(x1.x / a1, x1.y / a1) : make_float2(1.f, 0.f);
        float2 pc = make_float2(p0.x * p1.x + p0.y * p1.y, p0.y * p1.x - p0.x * p1.y); // p0*conj(p1)
#pragma unroll
        for (int s = 0; s < NSRC; s++) {
            float v0 = g_V[((s * 2 + 0) * FQ + f) * NT + tg] * ima;
            float v1 = g_V[((s * 2 + 1) * FQ + f) * NT + tg] * ima;
            r00[s] += v0 * v0;
            r11[s] += v1 * v1;
            float cr = v0 * v1;
            r01r[s] += cr * pc.x;
            r01i[s] += cr * pc.y;
            vs[s] += 0.5f * (v0 * v0 + v1 * v1);
        }
    }

    __shared__ float sacc[20][128];
#pragma unroll
    for (int s = 0; s < NSRC; s++) {
        sacc[s][tid] = r00[s];
        sacc[4 + s][tid] = r11[s];
        sacc[8 + s][tid] = r01r[s];
        sacc[12 + s][tid] = r01i[s];
        sacc[16 + s][tid] = vs[s];
    }
    __syncthreads();
    for (int off = 64; off; off >>= 1) {
        if (tid < off) {
#pragma unroll
            for (int q = 0; q < 20; q++) sacc[q][tid] += sacc[q][tid + off];
        }
        __syncthreads();
    }
    __shared__ float sR[16];
    if (tid < NSRC) {
        int s = tid;
        float denom = EPSV + sacc[16 + s][0];
        float inv = 1.0f / denom;
        sR[s * 4 + 0] = sacc[s][0] * inv;
        sR[s * 4 + 1] = sacc[4 + s][0] * inv;
        sR[s * 4 + 2] = sacc[8 + s][0] * inv;
        sR[s * 4 + 3] = sacc[12 + s][0] * inv;
    }
    __syncthreads();

    float R00[NSRC], R11[NSRC], R01x[NSRC], R01y[NSRC];
#pragma unroll
    for (int s = 0; s < NSRC; s++) {
        R00[s] = sR[s * 4 + 0];
        R11[s] = sR[s * 4 + 1];
        R01x[s] = sR[s * 4 + 2];
        R01y[s] = sR[s * 4 + 3];
    }

    // pass B: per-frame gain and output
    for (int t = tid; t < WINLEN; t += 128) {
        int tg = ck * WINLEN + t;
        float2 x0 = g_mix[(0 * FQ + f) * NT + tg];
        float2 x1 = g_mix[(1 * FQ + f) * NT + tg];
        float2 xs0 = make_float2(x0.x * ima, x0.y * ima);
        float2 xs1 = make_float2(x1.x * ima, x1.y * ima);

        float vloc[NSRC];
        float c00 = SQEPS, c11 = SQEPS, c01r = 0.f, c01i = 0.f;
#pragma unroll
        for (int s = 0; s < NSRC; s++) {
            float v0 = g_V[((s * 2 + 0) * FQ + f) * NT + tg] * ima;
            float v1 = g_V[((s * 2 + 1) * FQ + f) * NT + tg] * ima;
            float v = 0.5f * (v0 * v0 + v1 * v1);
            vloc[s] = v;
            c00 += v * R00[s];
            c11 += v * R11[s];
            c01r += v * R01x[s];
            c01i += v * R01y[s];
        }
        float det = c00 * c11 - (c01r * c01r + c01i * c01i);
        float idet = 1.0f / det;
        float i00 = c11 * idet, i11 = c00 * idet;
        float2 i01 = make_float2(-c01r * idet, -c01i * idet);
        float2 i10 = make_float2(-c01r * idet, c01i * idet);

#pragma unroll
        for (int s = 0; s < NSRC; s++) {
            float v = vloc[s];
            float a00 = R00[s], a11 = R11[s];
            float2 a01 = make_float2(R01x[s], R01y[s]);
            float2 a10 = make_float2(R01x[s], -R01y[s]); // conj
            // G = R * inv_Cxx * v
            float2 G00 = make_float2(a00 * i00 + a01.x * i10.x - a01.y * i10.y,
                                     a01.x * i10.y + a01.y * i10.x);
            float2 G01 = make_float2(a00 * i01.x + a01.x * i11,
                                     a00 * i01.y + a01.y * i11);
            float2 G10 = make_float2(a10.x * i00 + a11 * i10.x,
                                     a10.y * i00 + a11 * i10.y);
            float2 G11 = make_float2(a10.x * i01.x - a10.y * i01.y + a11 * i11,
                                     a10.x * i01.y + a10.y * i01.x);
            G00.x *= v; G00.y *= v; G01.x *= v; G01.y *= v;
            G10.x *= v; G10.y *= v; G11.x *= v; G11.y *= v;

            float2 y0 = cadd(cmul(G00, xs0), cmul(G01, xs1));
            float2 y1 = cadd(cmul(G10, xs0), cmul(G11, xs1));
            g_Y[((s * 2 + 0) * FQ + f) * NT + tg] = make_float2(y0.x * ma, y0.y * ma);
            g_Y[((s * 2 + 1) * FQ + f) * NT + tg] = make_float2(y1.x * ma, y1.y * ma);
        }
    }
}

// ---------------- ISTFT per frame: Hermitian extend, inverse FFT, window ----------------
__global__ __launch_bounds__(256) void istft_kernel() {
    __shared__ float2 sh[NFFT];
    int t = blockIdx.x, sc = blockIdx.y;
    for (int f = threadIdx.x; f <= NFFT / 2; f += 256) {
        float2 v = g_Y[(sc * FQ + f) * NT + t];
        sh[rev12(f)] = v;
        if (f > 0 && f < NFFT / 2) sh[rev12(NFFT - f)] = make_float2(v.x, -v.y);
    }
    __syncthreads();
    fft4096(sh, +1);
    float* outp = g_frames + (sc * NT + t) * NFFT;
    const float scale = 1.0f / NFFT;
    for (int n = threadIdx.x; n < NFFT; n += 256) {
        outp[n] = sh[n].x * scale * g_win[n];
    }
}

// ---------------- overlap-add gather + window-sum normalize + crop ----------------
__global__ __launch_bounds__(256) void gather_kernel(float* __restrict__ out) {
    int idx = blockIdx.x * blockDim.x + threadIdx.x;
    if (idx >= 8 * TLEN) return;
    int sc = idx / TLEN;
    int io = idx - sc * TLEN;
    int i = io + NFFT / 2;
    int tmin = (i - 3072) / 1024;   // ceil((i-4095)/1024), clamped below
    if (tmin < 0) tmin = 0;
    int tmax = i / HOP;
    if (tmax > NT - 1) tmax = NT - 1;
    float num = 0.f, den = 0.f;
    for (int tt = tmin; tt <= tmax; ++tt) {
        int n = i - tt * HOP;
        num += g_frames[(sc * NT + tt) * NFFT + n];
        float wv = g_win[n];
        den += wv * wv;
    }
    out[idx] = num / ((den > 1e-11f) ? den : 1.0f);
}

// ---------------- launch ----------------
extern "C" void kernel_launch(void* const* d_in, const int* in_sizes, int n_in,
                              void* d_out, int out_size) {
    const float* audio = (const float*)d_in[0];
    const float* Wmat = (const float*)d_in[1];
    float* out = (float*)d_out;

    init_kernel<<<16, 256>>>();
    stft_kernel<<<dim3(NT, 2), 256>>>(audio);
    gemm_kernel<<<dim3((NT + 63) / 64, (FQ + 63) / 64, 8), 256>>>(Wmat);
    wiener_kernel<<<dim3(FQ, NCHUNK), 128>>>();
    istft_kernel<<<dim3(NT, 8), 256>>>();
    gather_kernel<<<(8 * TLEN + 255) / 256, 256>>>(out);
}

// round 3
// speedup vs baseline: 1.5146x; 1.5146x over previous
#include <cuda_runtime.h>
#include <math.h>

// ---------------- problem constants ----------------
#define FQ     2049          // freq bins
#define NT     1500          // frames
#define TLEN   1535976       // audio samples
#define NFFT   4096
#define HOP    1024
#define NSRC   4
#define NCHUNK 5
#define WINLEN 300
#define EPSV   1e-10f
#define SQEPS  1e-5f

// ---------------- device scratch (static, no allocation) ----------------
__device__ float2 g_mix[2 * FQ * NT];          // STFT of mixture  [c][f][t]
__device__ float  g_mag[2 * FQ * NT];          // |mix|            [c][f][t]
__device__ float  g_V[8 * FQ * NT];            // targets          [s*2+c][f][t]
__device__ float2 g_Y[8 * FQ * NT];            // wiener output    [s*2+c][f][t]
__device__ float  g_frames[8 * NT * NFFT];     // windowed irfft frames
__device__ float2 g_tw[NFFT / 2];              // e^{-2pi i j/4096}
__device__ float  g_win[NFFT];                 // periodic hann
__device__ int    g_cmax[NCHUNK];              // per-chunk max|x| (float bits)

// ---------------- helpers ----------------
__device__ __forceinline__ float2 cmul(float2 a, float2 b) {
    return make_float2(a.x * b.x - a.y * b.y, a.x * b.y + a.y * b.x);
}
__device__ __forceinline__ float2 cadd(float2 a, float2 b) {
    return make_float2(a.x + b.x, a.y + b.y);
}
__device__ __forceinline__ int rev12(int n) { return (int)(__brev((unsigned)n) >> 20); }

__device__ __forceinline__ unsigned f2tf(float f) {
    unsigned r;
    asm("cvt.rna.tf32.f32 %0, %1;" : "=r"(r) : "f"(f));
    return r;
}

// in-place radix-2 DIT FFT, data pre-loaded bit-reversed in shared. sign=-1 fwd, +1 inv (unscaled)
__device__ void fft4096(float2* sh, int sign) {
    for (int half = 1; half <= 2048; half <<= 1) {
        int step = 2048 / half;
        for (int j = threadIdx.x; j < 2048; j += blockDim.x) {
            int k = j & (half - 1);
            int i0 = 2 * j - k;
            int i1 = i0 + half;
            float2 w = g_tw[k * step];
            if (sign > 0) w.y = -w.y;
            float2 u = sh[i0];
            float2 v = cmul(sh[i1], w);
            sh[i0] = make_float2(u.x + v.x, u.y + v.y);
            sh[i1] = make_float2(u.x - v.x, u.y - v.y);
        }
        __syncthreads();
    }
}

// ---------------- init: tables + chunk-max reset ----------------
__global__ void init_kernel() {
    int i = blockIdx.x * blockDim.x + threadIdx.x;
    if (i < NFFT / 2) {
        float s, c;
        sincospif(i * (1.0f / 2048.0f), &s, &c);
        g_tw[i] = make_float2(c, -s);
    }
    if (i < NFFT) {
        g_win[i] = 0.5f * (1.0f - cospif(i * (1.0f / 2048.0f)));
    }
    if (i < NCHUNK) g_cmax[i] = 0;
}

// ---------------- STFT (+ mag, + per-chunk max reduction) ----------------
__global__ __launch_bounds__(256) void stft_kernel(const float* __restrict__ audio) {
    __shared__ float2 sh[NFFT];
    __shared__ float smax[256];
    int t = blockIdx.x, c = blockIdx.y;
    for (int n = threadIdx.x; n < NFFT; n += 256) {
        int j = t * HOP + n - (NFFT / 2);
        if (j < 0) j = -j;
        if (j >= TLEN) j = 2 * (TLEN - 1) - j;
        float val = audio[c * TLEN + j] * g_win[n];
        sh[rev12(n)] = make_float2(val, 0.f);
    }
    __syncthreads();
    fft4096(sh, -1);
    float lmax = 0.f;
    for (int f = threadIdx.x; f <= NFFT / 2; f += 256) {
        float2 v = sh[f];
        int idx = (c * FQ + f) * NT + t;
        g_mix[idx] = v;
        float m = sqrtf(v.x * v.x + v.y * v.y);
        g_mag[idx] = m;
        lmax = fmaxf(lmax, m);
    }
    smax[threadIdx.x] = lmax;
    __syncthreads();
    for (int off = 128; off; off >>= 1) {
        if (threadIdx.x < off) smax[threadIdx.x] = fmaxf(smax[threadIdx.x], smax[threadIdx.x + off]);
        __syncthreads();
    }
    if (threadIdx.x == 0) atomicMax(&g_cmax[t / WINLEN], __float_as_int(smax[0]));
}

// ---------------- V = relu(W[s] @ mag[c])  via 3xTF32 tensor cores ----------------
// 8 GEMMs of [2049 x 1500 x 2049]. Block tile 128x128x16, 8 warps (2x4), warp tile 64x32.
// Each operand split a = a_hi + a_lo (both tf32); acc += hi*hi + hi*lo + lo*hi (fp32 acc).
__global__ __launch_bounds__(256) void gemm_tc_kernel(const float* __restrict__ Wmat) {
    const int sc = blockIdx.z;
    const float* A = Wmat + (sc >> 1) * FQ * FQ;   // [m=g][k=f] row-major
    const float* B = g_mag + (sc & 1) * FQ * NT;   // [k=f][n=t]
    float* C = g_V + sc * FQ * NT;                 // [m=g][n=t]

    __shared__ unsigned As[2][16][136];   // [hi/lo][k][m], tf32 bits, pad 136 (conflict-free frags)
    __shared__ unsigned Bs[2][16][136];   // [hi/lo][k][n]

    const int tid = threadIdx.x;
    const int lane = tid & 31, warp = tid >> 5;
    const int wm = (warp >> 2) * 64;   // warp m offset: 0 or 64
    const int wn = (warp & 3) * 32;    // warp n offset: 0,32,64,96
    const int row0 = blockIdx.y * 128, col0 = blockIdx.x * 128;

    const int a_row = tid >> 1;            // 0..127
    const int a_k = (tid & 1) * 8;         // 0 or 8
    const int b_col = lane * 4;            // 0..124
    const int b_row = warp;                // 0..7

    float acc[4][4][4];
#pragma unroll
    for (int i = 0; i < 4; i++)
#pragma unroll
        for (int j = 0; j < 4; j++)
#pragma unroll
            for (int q = 0; q < 4; q++) acc[i][j][q] = 0.f;

    const int grow = row0 + a_row;
    const bool gvalid = grow < FQ;
    const int fr = lane >> 2, kc = lane & 3;

    for (int k0 = 0; k0 < FQ; k0 += 16) {
        // stage A tile: A[row][k] -> As[k][row] transposed, hi/lo tf32 split
#pragma unroll
        for (int i = 0; i < 8; i++) {
            int k = k0 + a_k + i;
            float v = (gvalid && k < FQ) ? __ldg(&A[grow * FQ + k]) : 0.f;
            unsigned hb = f2tf(v);
            float lo = v - __uint_as_float(hb);
            As[0][a_k + i][a_row] = hb;
            As[1][a_k + i][a_row] = f2tf(lo);
        }
        // stage B tile: Bs[k][n], hi/lo tf32 split
#pragma unroll
        for (int r = 0; r < 2; r++) {
            int kk = b_row + r * 8;
            int k = k0 + kk;
            int col = col0 + b_col;
            float4 v = make_float4(0.f, 0.f, 0.f, 0.f);
            if (k < FQ) {
                if (col + 3 < NT) {
                    v = *(const float4*)&B[k * NT + col];
                } else {
                    if (col < NT)     v.x = B[k * NT + col];
                    if (col + 1 < NT) v.y = B[k * NT + col + 1];
                    if (col + 2 < NT) v.z = B[k * NT + col + 2];
                }
            }
            float e[4] = {v.x, v.y, v.z, v.w};
#pragma unroll
            for (int q = 0; q < 4; q++) {
                unsigned hb = f2tf(e[q]);
                float lo = e[q] - __uint_as_float(hb);
                Bs[0][kk][b_col + q] = hb;
                Bs[1][kk][b_col + q] = f2tf(lo);
            }
        }
        __syncthreads();

#pragma unroll
        for (int ks = 0; ks < 16; ks += 8) {
            unsigned ah[4][4], al[4][4];
#pragma unroll
            for (int i = 0; i < 4; i++) {
                int m = wm + i * 16;
                ah[i][0] = As[0][ks + kc][m + fr];
                ah[i][1] = As[0][ks + kc][m + fr + 8];
                ah[i][2] = As[0][ks + kc + 4][m + fr];
                ah[i][3] = As[0][ks + kc + 4][m + fr + 8];
                al[i][0] = As[1][ks + kc][m + fr];
                al[i][1] = As[1][ks + kc][m + fr + 8];
                al[i][2] = As[1][ks + kc + 4][m + fr];
                al[i][3] = As[1][ks + kc + 4][m + fr + 8];
            }
#pragma unroll
            for (int j = 0; j < 4; j++) {
                int n = wn + j * 8;
                unsigned bh0 = Bs[0][ks + kc][n + fr];
                unsigned bh1 = Bs[0][ks + kc + 4][n + fr];
                unsigned bl0 = Bs[1][ks + kc][n + fr];
                unsigned bl1 = Bs[1][ks + kc + 4][n + fr];
#pragma unroll
                for (int i = 0; i < 4; i++) {
                    asm volatile(
                        "mma.sync.aligned.m16n8k8.row.col.f32.tf32.tf32.f32 "
                        "{%0,%1,%2,%3}, {%4,%5,%6,%7}, {%8,%9}, {%0,%1,%2,%3};\n"
                        : "+f"(acc[i][j][0]), "+f"(acc[i][j][1]),
                          "+f"(acc[i][j][2]), "+f"(acc[i][j][3])
                        : "r"(ah[i][0]), "r"(ah[i][1]), "r"(ah[i][2]), "r"(ah[i][3]),
                          "r"(bl0), "r"(bl1));
                    asm volatile(
                        "mma.sync.aligned.m16n8k8.row.col.f32.tf32.tf32.f32 "
                        "{%0,%1,%2,%3}, {%4,%5,%6,%7}, {%8,%9}, {%0,%1,%2,%3};\n"
                        : "+f"(acc[i][j][0]), "+f"(acc[i][j][1]),
                          "+f"(acc[i][j][2]), "+f"(acc[i][j][3])
                        : "r"(al[i][0]), "r"(al[i][1]), "r"(al[i][2]), "r"(al[i][3]),
                          "r"(bh0), "r"(bh1));
                    asm volatile(
                        "mma.sync.aligned.m16n8k8.row.col.f32.tf32.tf32.f32 "
                        "{%0,%1,%2,%3}, {%4,%5,%6,%7}, {%8,%9}, {%0,%1,%2,%3};\n"
                        : "+f"(acc[i][j][0]), "+f"(acc[i][j][1]),
                          "+f"(acc[i][j][2]), "+f"(acc[i][j][3])
                        : "r"(ah[i][0]), "r"(ah[i][1]), "r"(ah[i][2]), "r"(ah[i][3]),
                          "r"(bh0), "r"(bh1));
                }
            }
        }
        __syncthreads();
    }

    // epilogue: relu + store
    const int cc = (lane & 3) * 2;
#pragma unroll
    for (int i = 0; i < 4; i++) {
        int row = row0 + wm + i * 16 + fr;
#pragma unroll
        for (int j = 0; j < 4; j++) {
            int col = col0 + wn + j * 8 + cc;
            if (row < FQ) {
                if (col < NT)     C[row * NT + col]     = fmaxf(acc[i][j][0], 0.f);
                if (col + 1 < NT) C[row * NT + col + 1] = fmaxf(acc[i][j][1], 0.f);
            }
            if (row + 8 < FQ) {
                if (col < NT)     C[(row + 8) * NT + col]     = fmaxf(acc[i][j][2], 0.f);
                if (col + 1 < NT) C[(row + 8) * NT + col + 1] = fmaxf(acc[i][j][3], 0.f);
            }
        }
    }
}

// ---------------- Wiener EM, 1 iteration, per (freq, chunk) ----------------
__global__ __launch_bounds__(128) void wiener_kernel() {
    const int f = blockIdx.x, ck = blockIdx.y;
    const int tid = threadIdx.x;
    const float ma = fmaxf(1.0f, __int_as_float(g_cmax[ck]) * 0.1f);
    const float ima = 1.0f / ma;

    // pass A: accumulate R (hermitian 2x2 per source) and sum_t v
    float r00[NSRC], r11[NSRC], r01r[NSRC], r01i[NSRC], vs[NSRC];
#pragma unroll
    for (int s = 0; s < NSRC; s++) { r00[s] = r11[s] = r01r[s] = r01i[s] = vs[s] = 0.f; }

    for (int t = tid; t < WINLEN; t += 128) {
        int tg = ck * WINLEN + t;
        float2 x0 = g_mix[(0 * FQ + f) * NT + tg];
        float2 x1 = g_mix[(1 * FQ + f) * NT + tg];
        float a0 = sqrtf(x0.x * x0.x + x0.y * x0.y);
        float a1 = sqrtf(x1.x * x1.x + x1.y * x1.y);
        float2 p0 = (a0 > 0.f) ? make_float2(x0.x / a0, x0.y / a0) : make_float2(1.f, 0.f);
        float2 p1 = (a1 > 0.f) ? make_float2(x1.x / a1, x1.y / a1) : make_float2(1.f, 0.f);
        float2 pc = make_float2(p0.x * p1.x + p0.y * p1.y, p0.y * p1.x - p0.x * p1.y); // p0*conj(p1)
#pragma unroll
        for (int s = 0; s < NSRC; s++) {
            float v0 = g_V[((s * 2 + 0) * FQ + f) * NT + tg] * ima;
            float v1 = g_V[((s * 2 + 1) * FQ + f) * NT + tg] * ima;
            r00[s] += v0 * v0;
            r11[s] += v1 * v1;
            float cr = v0 * v1;
            r01r[s] += cr * pc.x;
            r01i[s] += cr * pc.y;
            vs[s] += 0.5f * (v0 * v0 + v1 * v1);
        }
    }

    __shared__ float sacc[20][128];
#pragma unroll
    for (int s = 0; s < NSRC; s++) {
        sacc[s][tid] = r00[s];
        sacc[4 + s][tid] = r11[s];
        sacc[8 + s][tid] = r01r[s];
        sacc[12 + s][tid] = r01i[s];
        sacc[16 + s][tid] = vs[s];
    }
    __syncthreads();
    for (int off = 64; off; off >>= 1) {
        if (tid < off) {
#pragma unroll
            for (int q = 0; q < 20; q++) sacc[q][tid] += sacc[q][tid + off];
        }
        __syncthreads();
    }
    __shared__ float sR[16];
    if (tid < NSRC) {
        int s = tid;
        float denom = EPSV + sacc[16 + s][0];
        float inv = 1.0f / denom;
        sR[s * 4 + 0] = sacc[s][0] * inv;
        sR[s * 4 + 1] = sacc[4 + s][0] * inv;
        sR[s * 4 + 2] = sacc[8 + s][0] * inv;
        sR[s * 4 + 3] = sacc[12 + s][0] * inv;
    }
    __syncthreads();

    float R00[NSRC], R11[NSRC], R01x[NSRC], R01y[NSRC];
#pragma unroll
    for (int s = 0; s < NSRC; s++) {
        R00[s] = sR[s * 4 + 0];
        R11[s] = sR[s * 4 + 1];
        R01x[s] = sR[s * 4 + 2];
        R01y[s] = sR[s * 4 + 3];
    }

    // pass B: per-frame gain and output
    for (int t = tid; t < WINLEN; t += 128) {
        int tg = ck * WINLEN + t;
        float2 x0 = g_mix[(0 * FQ + f) * NT + tg];
        float2 x1 = g_mix[(1 * FQ + f) * NT + tg];
        float2 xs0 = make_float2(x0.x * ima, x0.y * ima);
        float2 xs1 = make_float2(x1.x * ima, x1.y * ima);

        float vloc[NSRC];
        float c00 = SQEPS, c11 = SQEPS, c01r = 0.f, c01i = 0.f;
#pragma unroll
        for (int s = 0; s < NSRC; s++) {
            float v0 = g_V[((s * 2 + 0) * FQ + f) * NT + tg] * ima;
            float v1 = g_V[((s * 2 + 1) * FQ + f) * NT + tg] * ima;
            float v = 0.5f * (v0 * v0 + v1 * v1);
            vloc[s] = v;
            c00 += v * R00[s];
            c11 += v * R11[s];
            c01r += v * R01x[s];
            c01i += v * R01y[s];
        }
        float det = c00 * c11 - (c01r * c01r + c01i * c01i);
        float idet = 1.0f / det;
        float i00 = c11 * idet, i11 = c00 * idet;
        float2 i01 = make_float2(-c01r * idet, -c01i * idet);
        float2 i10 = make_float2(-c01r * idet, c01i * idet);

#pragma unroll
        for (int s = 0; s < NSRC; s++) {
            float v = vloc[s];
            float a00 = R00[s], a11 = R11[s];
            float2 a01 = make_float2(R01x[s], R01y[s]);
            float2 a10 = make_float2(R01x[s], -R01y[s]); // conj
            // G = R * inv_Cxx * v
            float2 G00 = make_float2(a00 * i00 + a01.x * i10.x - a01.y * i10.y,
                                     a01.x * i10.y + a01.y * i10.x);
            float2 G01 = make_float2(a00 * i01.x + a01.x * i11,
                                     a00 * i01.y + a01.y * i11);
            float2 G10 = make_float2(a10.x * i00 + a11 * i10.x,
                                     a10.y * i00 + a11 * i10.y);
            float2 G11 = make_float2(a10.x * i01.x - a10.y * i01.y + a11 * i11,
                                     a10.x * i01.y + a10.y * i01.x);
            G00.x *= v; G00.y *= v; G01.x *= v; G01.y *= v;
            G10.x *= v; G10.y *= v; G11.x *= v; G11.y *= v;

            float2 y0 = cadd(cmul(G00, xs0), cmul(G01, xs1));
            float2 y1 = cadd(cmul(G10, xs0), cmul(G11, xs1));
            g_Y[((s * 2 + 0) * FQ + f) * NT + tg] = make_float2(y0.x * ma, y0.y * ma);
            g_Y[((s * 2 + 1) * FQ + f) * NT + tg] = make_float2(y1.x * ma, y1.y * ma);
        }
    }
}

// ---------------- ISTFT per frame: Hermitian extend, inverse FFT, window ----------------
__global__ __launch_bounds__(256) void istft_kernel() {
    __shared__ float2 sh[NFFT];
    int t = blockIdx.x, sc = blockIdx.y;
    for (int f = threadIdx.x; f <= NFFT / 2; f += 256) {
        float2 v = g_Y[(sc * FQ + f) * NT + t];
        sh[rev12(f)] = v;
        if (f > 0 && f < NFFT / 2) sh[rev12(NFFT - f)] = make_float2(v.x, -v.y);
    }
    __syncthreads();
    fft4096(sh, +1);
    float* outp = g_frames + (sc * NT + t) * NFFT;
    const float scale = 1.0f / NFFT;
    for (int n = threadIdx.x; n < NFFT; n += 256) {
        outp[n] = sh[n].x * scale * g_win[n];
    }
}

// ---------------- overlap-add gather + window-sum normalize + crop ----------------
__global__ __launch_bounds__(256) void gather_kernel(float* __restrict__ out) {
    int idx = blockIdx.x * blockDim.x + threadIdx.x;
    if (idx >= 8 * TLEN) return;
    int sc = idx / TLEN;
    int io = idx - sc * TLEN;
    int i = io + NFFT / 2;
    int tmin = (i - 3072) / 1024;   // ceil((i-4095)/1024), clamped below
    if (tmin < 0) tmin = 0;
    int tmax = i / HOP;
    if (tmax > NT - 1) tmax = NT - 1;
    float num = 0.f, den = 0.f;
    for (int tt = tmin; tt <= tmax; ++tt) {
        int n = i - tt * HOP;
        num += g_frames[(sc * NT + tt) * NFFT + n];
        float wv = g_win[n];
        den += wv * wv;
    }
    out[idx] = num / ((den > 1e-11f) ? den : 1.0f);
}

// ---------------- launch ----------------
extern "C" void kernel_launch(void* const* d_in, const int* in_sizes, int n_in,
                              void* d_out, int out_size) {
    const float* audio = (const float*)d_in[0];
    const float* Wmat = (const float*)d_in[1];
    float* out = (float*)d_out;

    init_kernel<<<16, 256>>>();
    stft_kernel<<<dim3(NT, 2), 256>>>(audio);
    gemm_tc_kernel<<<dim3((NT + 127) / 128, (FQ + 127) / 128, 8), 256>>>(Wmat);
    wiener_kernel<<<dim3(FQ, NCHUNK), 128>>>();
    istft_kernel<<<dim3(NT, 8), 256>>>();
    gather_kernel<<<(8 * TLEN + 255) / 256, 256>>>(out);
}

// round 4
// speedup vs baseline: 1.7890x; 1.1812x over previous
#include <cuda_runtime.h>
#include <math.h>

// ---------------- problem constants ----------------
#define FQ     2049
#define NT     1500
#define TLEN   1535976
#define NFFT   4096
#define HOP    1024
#define NSRC   4
#define NCHUNK 5
#define WINLEN 300
#define EPSV   1e-10f
#define SQEPS  1e-5f

// ---------------- device scratch ----------------
__device__ float2 g_mix[2 * FQ * NT];          // [c][f][t]
__device__ float  g_mag[2 * FQ * NT];          // [c][f][t]
__device__ float  g_V[8 * FQ * NT];            // [s*2+c][f][t]
__device__ float2 g_Y[8 * FQ * NT];            // [s*2+c][f][t]
__device__ float  g_frames[8 * NT * NFFT];
__device__ float2 g_tw[3072];                  // e^{-2pi i j/4096}, j<3072 (radix-4 needs 3k)
__device__ float  g_win[NFFT];
__device__ int    g_cmax[NCHUNK];

// ---------------- helpers ----------------
__device__ __forceinline__ float2 cmul(float2 a, float2 b) {
    return make_float2(a.x * b.x - a.y * b.y, a.x * b.y + a.y * b.x);
}
__device__ __forceinline__ float2 cadd(float2 a, float2 b) {
    return make_float2(a.x + b.x, a.y + b.y);
}
// base-4 digit reversal of 12-bit index
__device__ __forceinline__ int rev4(int n) {
    unsigned r = __brev((unsigned)n) >> 20;
    return (int)(((r & 0x555u) << 1) | ((r >> 1) & 0x555u));
}
__device__ __forceinline__ unsigned f2tf(float f) {
    unsigned r;
    asm("cvt.rna.tf32.f32 %0, %1;" : "=r"(r) : "f"(f));
    return r;
}

// in-place radix-4 DIT FFT4096, input pre-loaded in base-4-digit-reversed order.
// sign=-1 forward, +1 inverse (unscaled). 6 stages.
__device__ void fft4096_r4(float2* sh, int sign) {
#pragma unroll
    for (int st = 0; st < 6; st++) {
        const int q = 1 << (2 * st);
        const int stepT = 1024 >> (2 * st);
        for (int j = threadIdx.x; j < 1024; j += 256) {
            int k = j & (q - 1);
            int base = ((j - k) << 2) + k;
            float2 w1 = g_tw[k * stepT];
            float2 w2 = g_tw[2 * k * stepT];
            float2 w3 = g_tw[3 * k * stepT];
            if (sign > 0) { w1.y = -w1.y; w2.y = -w2.y; w3.y = -w3.y; }
            float2 a0 = sh[base];
            float2 a1 = cmul(sh[base + q], w1);
            float2 a2 = cmul(sh[base + 2 * q], w2);
            float2 a3 = cmul(sh[base + 3 * q], w3);
            float2 b0 = make_float2(a0.x + a2.x, a0.y + a2.y);
            float2 b1 = make_float2(a0.x - a2.x, a0.y - a2.y);
            float2 b2 = make_float2(a1.x + a3.x, a1.y + a3.y);
            float2 b3 = make_float2(a1.x - a3.x, a1.y - a3.y);
            float2 rot = (sign < 0) ? make_float2(b3.y, -b3.x)   // -j*b3
                                    : make_float2(-b3.y, b3.x);  // +j*b3
            sh[base]         = make_float2(b0.x + b2.x, b0.y + b2.y);
            sh[base + q]     = make_float2(b1.x + rot.x, b1.y + rot.y);
            sh[base + 2 * q] = make_float2(b0.x - b2.x, b0.y - b2.y);
            sh[base + 3 * q] = make_float2(b1.x - rot.x, b1.y - rot.y);
        }
        __syncthreads();
    }
}

// ---------------- init ----------------
__global__ void init_kernel() {
    int i = blockIdx.x * blockDim.x + threadIdx.x;
    if (i < 3072) {
        float s, c;
        sincospif(i * (1.0f / 2048.0f), &s, &c);
        g_tw[i] = make_float2(c, -s);
    }
    if (i < NFFT) {
        g_win[i] = 0.5f * (1.0f - cospif(i * (1.0f / 2048.0f)));
    }
    if (i < NCHUNK) g_cmax[i] = 0;
}

// ---------------- STFT: both channels packed in one complex FFT ----------------
__global__ __launch_bounds__(256) void stft_kernel(const float* __restrict__ audio) {
    __shared__ float2 sh[NFFT];
    __shared__ float smax[256];
    int t = blockIdx.x;
    for (int n = threadIdx.x; n < NFFT; n += 256) {
        int j = t * HOP + n - (NFFT / 2);
        if (j < 0) j = -j;
        if (j >= TLEN) j = 2 * (TLEN - 1) - j;
        float w = g_win[n];
        sh[rev4(n)] = make_float2(audio[j] * w, audio[TLEN + j] * w);
    }
    __syncthreads();
    fft4096_r4(sh, -1);
    float lmax = 0.f;
    for (int f = threadIdx.x; f <= NFFT / 2; f += 256) {
        float2 A = sh[f];
        float2 Zn = sh[(NFFT - f) & (NFFT - 1)];
        // X0 = 0.5(A + conj(Zn));  X1 = 0.5(A.y+Zn.y, Zn.x-A.x)
        float2 x0 = make_float2(0.5f * (A.x + Zn.x), 0.5f * (A.y - Zn.y));
        float2 x1 = make_float2(0.5f * (A.y + Zn.y), 0.5f * (Zn.x - A.x));
        int i0 = (0 * FQ + f) * NT + t;
        int i1 = (1 * FQ + f) * NT + t;
        g_mix[i0] = x0;
        g_mix[i1] = x1;
        float m0 = sqrtf(x0.x * x0.x + x0.y * x0.y);
        float m1 = sqrtf(x1.x * x1.x + x1.y * x1.y);
        g_mag[i0] = m0;
        g_mag[i1] = m1;
        lmax = fmaxf(lmax, fmaxf(m0, m1));
    }
    smax[threadIdx.x] = lmax;
    __syncthreads();
    for (int off = 128; off; off >>= 1) {
        if (threadIdx.x < off) smax[threadIdx.x] = fmaxf(smax[threadIdx.x], smax[threadIdx.x + off]);
        __syncthreads();
    }
    if (threadIdx.x == 0) atomicMax(&g_cmax[t / WINLEN], __float_as_int(smax[0]));
}

// ---------------- V = relu(W[s] @ mag[c]) : pipelined 3xTF32 MMA ----------------
// Block tile 128x128x16, double-buffered fp32 smem, hi/lo split at fragment load.
__global__ __launch_bounds__(256) void gemm_tc_kernel(const float* __restrict__ Wmat) {
    const int sc = blockIdx.z;
    const float* A = Wmat + (sc >> 1) * FQ * FQ;   // [m][k]
    const float* B = g_mag + (sc & 1) * FQ * NT;   // [k][n]
    float* C = g_V + sc * FQ * NT;                 // [m][n]

    __shared__ float As[2][16][136];   // [buf][k][m]
    __shared__ float Bs[2][16][136];   // [buf][k][n]

    const int tid = threadIdx.x;
    const int lane = tid & 31, warp = tid >> 5;
    const int wm = (warp >> 2) * 64;
    const int wn = (warp & 3) * 32;
    const int row0 = blockIdx.y * 128, col0 = blockIdx.x * 128;

    const int a_row = tid >> 1;          // 0..127
    const int a_k = (tid & 1) * 8;       // 0 or 8
    const int b_col = lane * 4;          // 0..124
    const int b_row = warp;              // 0..7

    const int grow = row0 + a_row;
    const bool gvalid = grow < FQ;
    const int fr = lane >> 2, kc = lane & 3;

    float acc[4][4][4];
#pragma unroll
    for (int i = 0; i < 4; i++)
#pragma unroll
        for (int j = 0; j < 4; j++)
#pragma unroll
            for (int q = 0; q < 4; q++) acc[i][j][q] = 0.f;

    float pa[8];
    float4 pb[2];

    // tile loaders: gmem -> regs
    auto load_regs = [&](int k0) {
#pragma unroll
        for (int i = 0; i < 8; i++) {
            int k = k0 + a_k + i;
            pa[i] = (gvalid && k < FQ) ? __ldg(&A[grow * FQ + k]) : 0.f;
        }
#pragma unroll
        for (int r = 0; r < 2; r++) {
            int k = k0 + b_row + r * 8;
            int col = col0 + b_col;
            float4 v = make_float4(0.f, 0.f, 0.f, 0.f);
            if (k < FQ) {
                if (col + 3 < NT) {
                    v = *(const float4*)&B[k * NT + col];
                } else {
                    if (col < NT)     v.x = B[k * NT + col];
                    if (col + 1 < NT) v.y = B[k * NT + col + 1];
                    if (col + 2 < NT) v.z = B[k * NT + col + 2];
                }
            }
            pb[r] = v;
        }
    };
    auto store_smem = [&](int buf) {
#pragma unroll
        for (int i = 0; i < 8; i++) As[buf][a_k + i][a_row] = pa[i];
#pragma unroll
        for (int r = 0; r < 2; r++) {
            int kk = b_row + r * 8;
            Bs[buf][kk][b_col]     = pb[r].x;
            Bs[buf][kk][b_col + 1] = pb[r].y;
            Bs[buf][kk][b_col + 2] = pb[r].z;
            Bs[buf][kk][b_col + 3] = pb[r].w;
        }
    };

    load_regs(0);
    store_smem(0);
    __syncthreads();

    int buf = 0;
    for (int k0 = 0; k0 < FQ; k0 += 16) {
        const bool has_next = (k0 + 16 < FQ);
        if (has_next) load_regs(k0 + 16);

#pragma unroll
        for (int ks = 0; ks < 16; ks += 8) {
            unsigned ah[4][4], al[4][4];
#pragma unroll
            for (int i = 0; i < 4; i++) {
                int m = wm + i * 16;
#pragma unroll
                for (int q = 0; q < 4; q++) {
                    float v = As[buf][ks + kc + (q >> 1) * 4][m + fr + (q & 1) * 8];
                    unsigned hb = f2tf(v);
                    ah[i][q] = hb;
                    al[i][q] = f2tf(v - __uint_as_float(hb));
                }
            }
#pragma unroll
            for (int j = 0; j < 4; j++) {
                int n = wn + j * 8;
                float v0 = Bs[buf][ks + kc][n + fr];
                float v1 = Bs[buf][ks + kc + 4][n + fr];
                unsigned bh0 = f2tf(v0), bh1 = f2tf(v1);
                unsigned bl0 = f2tf(v0 - __uint_as_float(bh0));
                unsigned bl1 = f2tf(v1 - __uint_as_float(bh1));
#pragma unroll
                for (int i = 0; i < 4; i++) {
                    asm volatile(
                        "mma.sync.aligned.m16n8k8.row.col.f32.tf32.tf32.f32 "
                        "{%0,%1,%2,%3}, {%4,%5,%6,%7}, {%8,%9}, {%0,%1,%2,%3};\n"
                        : "+f"(acc[i][j][0]), "+f"(acc[i][j][1]),
                          "+f"(acc[i][j][2]), "+f"(acc[i][j][3])
                        : "r"(ah[i][0]), "r"(ah[i][1]), "r"(ah[i][2]), "r"(ah[i][3]),
                          "r"(bl0), "r"(bl1));
                    asm volatile(
                        "mma.sync.aligned.m16n8k8.row.col.f32.tf32.tf32.f32 "
                        "{%0,%1,%2,%3}, {%4,%5,%6,%7}, {%8,%9}, {%0,%1,%2,%3};\n"
                        : "+f"(acc[i][j][0]), "+f"(acc[i][j][1]),
                          "+f"(acc[i][j][2]), "+f"(acc[i][j][3])
                        : "r"(al[i][0]), "r"(al[i][1]), "r"(al[i][2]), "r"(al[i][3]),
                          "r"(bh0), "r"(bh1));
                    asm volatile(
                        "mma.sync.aligned.m16n8k8.row.col.f32.tf32.tf32.f32 "
                        "{%0,%1,%2,%3}, {%4,%5,%6,%7}, {%8,%9}, {%0,%1,%2,%3};\n"
                        : "+f"(acc[i][j][0]), "+f"(acc[i][j][1]),
                          "+f"(acc[i][j][2]), "+f"(acc[i][j][3])
                        : "r"(ah[i][0]), "r"(ah[i][1]), "r"(ah[i][2]), "r"(ah[i][3]),
                          "r"(bh0), "r"(bh1));
                }
            }
        }
        if (has_next) {
            store_smem(buf ^ 1);
            __syncthreads();
            buf ^= 1;
        }
    }

    // epilogue: relu + store (float2 per pair of adjacent cols)
    const int cc = (lane & 3) * 2;
#pragma unroll
    for (int i = 0; i < 4; i++) {
        int row = row0 + wm + i * 16 + fr;
#pragma unroll
        for (int j = 0; j < 4; j++) {
            int col = col0 + wn + j * 8 + cc;
            if (row < FQ && col + 1 < NT) {
                *(float2*)&C[row * NT + col] =
                    make_float2(fmaxf(acc[i][j][0], 0.f), fmaxf(acc[i][j][1], 0.f));
            } else if (row < FQ && col < NT) {
                C[row * NT + col] = fmaxf(acc[i][j][0], 0.f);
            }
            if (row + 8 < FQ && col + 1 < NT) {
                *(float2*)&C[(row + 8) * NT + col] =
                    make_float2(fmaxf(acc[i][j][2], 0.f), fmaxf(acc[i][j][3], 0.f));
            } else if (row + 8 < FQ && col < NT) {
                C[(row + 8) * NT + col] = fmaxf(acc[i][j][2], 0.f);
            }
        }
    }
}

// ---------------- Wiener EM ----------------
__global__ __launch_bounds__(128) void wiener_kernel() {
    const int f = blockIdx.x, ck = blockIdx.y;
    const int tid = threadIdx.x;
    const float ma = fmaxf(1.0f, __int_as_float(g_cmax[ck]) * 0.1f);
    const float ima = 1.0f / ma;

    float r00[NSRC], r11[NSRC], r01r[NSRC], r01i[NSRC], vs[NSRC];
#pragma unroll
    for (int s = 0; s < NSRC; s++) { r00[s] = r11[s] = r01r[s] = r01i[s] = vs[s] = 0.f; }

    for (int t = tid; t < WINLEN; t += 128) {
        int tg = ck * WINLEN + t;
        float2 x0 = g_mix[(0 * FQ + f) * NT + tg];
        float2 x1 = g_mix[(1 * FQ + f) * NT + tg];
        float a0 = sqrtf(x0.x * x0.x + x0.y * x0.y);
        float a1 = sqrtf(x1.x * x1.x + x1.y * x1.y);
        float2 p0 = (a0 > 0.f) ? make_float2(x0.x / a0, x0.y / a0) : make_float2(1.f, 0.f);
        float2 p1 = (a1 > 0.f) ? make_float2(x1.x / a1, x1.y / a1) : make_float2(1.f, 0.f);
        float2 pc = make_float2(p0.x * p1.x + p0.y * p1.y, p0.y * p1.x - p0.x * p1.y);
#pragma unroll
        for (int s = 0; s < NSRC; s++) {
            float v0 = g_V[((s * 2 + 0) * FQ + f) * NT + tg] * ima;
            float v1 = g_V[((s * 2 + 1) * FQ + f) * NT + tg] * ima;
            r00[s] += v0 * v0;
            r11[s] += v1 * v1;
            float cr = v0 * v1;
            r01r[s] += cr * pc.x;
            r01i[s] += cr * pc.y;
            vs[s] += 0.5f * (v0 * v0 + v1 * v1);
        }
    }

    __shared__ float sacc[20][128];
#pragma unroll
    for (int s = 0; s < NSRC; s++) {
        sacc[s][tid] = r00[s];
        sacc[4 + s][tid] = r11[s];
        sacc[8 + s][tid] = r01r[s];
        sacc[12 + s][tid] = r01i[s];
        sacc[16 + s][tid] = vs[s];
    }
    __syncthreads();
    for (int off = 64; off; off >>= 1) {
        if (tid < off) {
#pragma unroll
            for (int q = 0; q < 20; q++) sacc[q][tid] += sacc[q][tid + off];
        }
        __syncthreads();
    }
    __shared__ float sR[16];
    if (tid < NSRC) {
        int s = tid;
        float inv = 1.0f / (EPSV + sacc[16 + s][0]);
        sR[s * 4 + 0] = sacc[s][0] * inv;
        sR[s * 4 + 1] = sacc[4 + s][0] * inv;
        sR[s * 4 + 2] = sacc[8 + s][0] * inv;
        sR[s * 4 + 3] = sacc[12 + s][0] * inv;
    }
    __syncthreads();

    float R00[NSRC], R11[NSRC], R01x[NSRC], R01y[NSRC];
#pragma unroll
    for (int s = 0; s < NSRC; s++) {
        R00[s] = sR[s * 4 + 0];
        R11[s] = sR[s * 4 + 1];
        R01x[s] = sR[s * 4 + 2];
        R01y[s] = sR[s * 4 + 3];
    }

    for (int t = tid; t < WINLEN; t += 128) {
        int tg = ck * WINLEN + t;
        float2 x0 = g_mix[(0 * FQ + f) * NT + tg];
        float2 x1 = g_mix[(1 * FQ + f) * NT + tg];
        float2 xs0 = make_float2(x0.x * ima, x0.y * ima);
        float2 xs1 = make_float2(x1.x * ima, x1.y * ima);

        float vloc[NSRC];
        float c00 = SQEPS, c11 = SQEPS, c01r = 0.f, c01i = 0.f;
#pragma unroll
        for (int s = 0; s < NSRC; s++) {
            float v0 = g_V[((s * 2 + 0) * FQ + f) * NT + tg] * ima;
            float v1 = g_V[((s * 2 + 1) * FQ + f) * NT + tg] * ima;
            float v = 0.5f * (v0 * v0 + v1 * v1);
            vloc[s] = v;
            c00 += v * R00[s];
            c11 += v * R11[s];
            c01r += v * R01x[s];
            c01i += v * R01y[s];
        }
        float det = c00 * c11 - (c01r * c01r + c01i * c01i);
        float idet = 1.0f / det;
        float i00 = c11 * idet, i11 = c00 * idet;
        float2 i01 = make_float2(-c01r * idet, -c01i * idet);
        float2 i10 = make_float2(-c01r * idet, c01i * idet);

#pragma unroll
        for (int s = 0; s < NSRC; s++) {
            float v = vloc[s];
            float a00 = R00[s], a11 = R11[s];
            float2 a01 = make_float2(R01x[s], R01y[s]);
            float2 a10 = make_float2(R01x[s], -R01y[s]);
            float2 G00 = make_float2(a00 * i00 + a01.x * i10.x - a01.y * i10.y,
                                     a01.x * i10.y + a01.y * i10.x);
            float2 G01 = make_float2(a00 * i01.x + a01.x * i11,
                                     a00 * i01.y + a01.y * i11);
            float2 G10 = make_float2(a10.x * i00 + a11 * i10.x,
                                     a10.y * i00 + a11 * i10.y);
            float2 G11 = make_float2(a10.x * i01.x - a10.y * i01.y + a11 * i11,
                                     a10.x * i01.y + a10.y * i01.x);
            G00.x *= v; G00.y *= v; G01.x *= v; G01.y *= v;
            G10.x *= v; G10.y *= v; G11.x *= v; G11.y *= v;

            float2 y0 = cadd(cmul(G00, xs0), cmul(G01, xs1));
            float2 y1 = cadd(cmul(G10, xs0), cmul(G11, xs1));
            g_Y[((s * 2 + 0) * FQ + f) * NT + tg] = make_float2(y0.x * ma, y0.y * ma);
            g_Y[((s * 2 + 1) * FQ + f) * NT + tg] = make_float2(y1.x * ma, y1.y * ma);
        }
    }
}

// ---------------- ISTFT: channel pair (2 real outputs) per complex inverse FFT ----------------
__global__ __launch_bounds__(256) void istft_kernel() {
    __shared__ float2 sh[NFFT];
    int t = blockIdx.x, s = blockIdx.y;
    for (int f = threadIdx.x; f <= NFFT / 2; f += 256) {
        float2 y0 = g_Y[((s * 2 + 0) * FQ + f) * NT + t];
        float2 y1 = g_Y[((s * 2 + 1) * FQ + f) * NT + t];
        // Z[f] = Y0 + i*Y1 ; Z[N-f] = conj(Y0) + i*conj(Y1)
        sh[rev4(f)] = make_float2(y0.x - y1.y, y0.y + y1.x);
        if (f > 0 && f < NFFT / 2)
            sh[rev4(NFFT - f)] = make_float2(y0.x + y1.y, y1.x - y0.y);
    }
    __syncthreads();
    fft4096_r4(sh, +1);
    float* out0 = g_frames + ((s * 2 + 0) * NT + t) * NFFT;
    float* out1 = g_frames + ((s * 2 + 1) * NT + t) * NFFT;
    const float scale = 1.0f / NFFT;
    for (int n = threadIdx.x; n < NFFT; n += 256) {
        float2 z = sh[n];
        float ws = scale * g_win[n];
        out0[n] = z.x * ws;
        out1[n] = z.y * ws;
    }
}

// ---------------- overlap-add gather ----------------
__global__ __launch_bounds__(256) void gather_kernel(float* __restrict__ out) {
    int idx = blockIdx.x * blockDim.x + threadIdx.x;
    if (idx >= 8 * TLEN) return;
    int sc = idx / TLEN;
    int io = idx - sc * TLEN;
    int i = io + NFFT / 2;
    int tmin = (i - 3072) / 1024;
    if (tmin < 0) tmin = 0;
    int tmax = i / HOP;
    if (tmax > NT - 1) tmax = NT - 1;
    float num = 0.f, den = 0.f;
    for (int tt = tmin; tt <= tmax; ++tt) {
        int n = i - tt * HOP;
        num += g_frames[(sc * NT + tt) * NFFT + n];
        float wv = g_win[n];
        den += wv * wv;
    }
    out[idx] = num / ((den > 1e-11f) ? den : 1.0f);
}

// ---------------- launch ----------------
extern "C" void kernel_launch(void* const* d_in, const int* in_sizes, int n_in,
                              void* d_out, int out_size) {
    const float* audio = (const float*)d_in[0];
    const float* Wmat = (const float*)d_in[1];
    float* out = (float*)d_out;

    init_kernel<<<16, 256>>>();
    stft_kernel<<<NT, 256>>>(audio);
    gemm_tc_kernel<<<dim3((NT + 127) / 128, (FQ + 127) / 128, 8), 256>>>(Wmat);
    wiener_kernel<<<dim3(FQ, NCHUNK), 128>>>();
    istft_kernel<<<dim3(NT, NSRC), 256>>>();
    gather_kernel<<<(8 * TLEN + 255) / 256, 256>>>(out);
}